// round 17
// baseline (speedup 1.0000x reference)
#include <cuda_runtime.h>
#include <cuda_bf16.h>
#include <cstdint>

// ============================================================================
// Induction capsule routing, restructured (no e materialization):
//   c_i = (sum_s d_is x_is) @ W      (u_kernel; gemm NT)
//   b  += co * (x . (W c_raw))       (gemm TN; squash folded into fused b_update)
// Split-K(16) GEMM on mma.sync m16n8k16 bf16, 3-product bf16x2 split.
// ALL splitting hoisted out of the gemm: W pre-packed once per call into the
// gemm's smem element format (uint2 {hi,lo}); u and c packed by their producers.
// Gemm staging = pure LDG.128 -> STS.128 (conflict-free); inner loop LDS.64+HMMA.
// ============================================================================

static constexpr int C_CAPS = 64;
static constexpr int S_LEN  = 128;
static constexpr int H_DIM  = 2048;
static constexpr int KPH    = H_DIM / 2;        // 1024 k-pairs per row
static constexpr int KSPLIT = 16;
static constexpr int KLEN   = H_DIM / KSPLIT;   // 128 -> 4 chunks of 32
static constexpr int NCHUNK = KLEN / 32;        // 4
static constexpr int KPC    = 16;               // k-pairs per chunk

// ---- scratch (device globals; allocation-free rule) ----
__device__ float g_b[C_CAPS * S_LEN];                       // logits
__device__ float g_part[KSPLIT][C_CAPS][H_DIM];             // split-K partials (8 MB)
__device__ float g_nrm2[C_CAPS][16];                        // per-block norm partials
__device__ uint2 g_Wtn[(size_t)H_DIM * KPH];                // W packed, k-pairs in-row (16 MB)
__device__ uint2 g_Wnt[(size_t)KPH * H_DIM];                // W packed, k-pairs cross-row (16 MB)
__device__ uint2 g_usp[C_CAPS * KPH];                       // u packed (512 KB)
__device__ uint2 g_csp[C_CAPS * KPH];                       // c_raw packed (512 KB)

// ============================================================================
// bf16 split/pack helpers
// ============================================================================
static __device__ __forceinline__ void pack_split(float e, float o,
                                                  uint32_t& hi, uint32_t& lo) {
    __nv_bfloat162 h = __floats2bfloat162_rn(e, o);           // x=e(k even), y=o(k odd)
    float re = e - __bfloat162float(h.x);
    float ro = o - __bfloat162float(h.y);
    __nv_bfloat162 l = __floats2bfloat162_rn(re, ro);
    hi = *(uint32_t*)&h;
    lo = *(uint32_t*)&l;
}
static __device__ __forceinline__ void mma_bf16(float* c, const uint32_t* a,
                                                uint32_t b0, uint32_t b1) {
    asm("mma.sync.aligned.m16n8k16.row.col.f32.bf16.bf16.f32 "
        "{%0,%1,%2,%3}, {%4,%5,%6,%7}, {%8,%9}, {%0,%1,%2,%3};"
        : "+f"(c[0]), "+f"(c[1]), "+f"(c[2]), "+f"(c[3])
        : "r"(a[0]), "r"(a[1]), "r"(a[2]), "r"(a[3]), "r"(b0), "r"(b1));
}

// ============================================================================
// W precompute (once per call):
//   g_Wtn[j][kp] = pack(W[j][2kp], W[j][2kp+1])     (TN B operand)
//   g_Wnt[kp][j] = pack(W[2kp][j], W[2kp+1][j])     (NT B operand)
// ============================================================================
__global__ void __launch_bounds__(256) pre_tn_kernel(const float* __restrict__ W) {
    const int idx = blockIdx.x * 256 + threadIdx.x;       // 0 .. 2048*512-1
    const int j = idx >> 9, kg = idx & 511;
    float4 v = *(const float4*)(W + (size_t)j * H_DIM + kg * 4);
    uint32_t h0, l0, h1, l1;
    pack_split(v.x, v.y, h0, l0);
    pack_split(v.z, v.w, h1, l1);
    *(uint4*)&g_Wtn[(size_t)j * KPH + kg * 2] = make_uint4(h0, l0, h1, l1);
}
__global__ void __launch_bounds__(256) pre_nt_kernel(const float* __restrict__ W) {
    const int idx = blockIdx.x * 256 + threadIdx.x;       // 0 .. 1024*512-1
    const int kp = idx >> 9, jg = idx & 511;
    float4 r0 = *(const float4*)(W + (size_t)(2 * kp) * H_DIM + jg * 4);
    float4 r1 = *(const float4*)(W + (size_t)(2 * kp + 1) * H_DIM + jg * 4);
    uint32_t h0, l0, h1, l1;
    pack_split(r0.x, r1.x, h0, l0);
    pack_split(r0.y, r1.y, h1, l1);
    *(uint4*)&g_Wnt[(size_t)kp * H_DIM + jg * 4] = make_uint4(h0, l0, h1, l1);
    pack_split(r0.z, r1.z, h0, l0);
    pack_split(r0.w, r1.w, h1, l1);
    *(uint4*)&g_Wnt[(size_t)kp * H_DIM + jg * 4 + 2] = make_uint4(h0, l0, h1, l1);
}

// ============================================================================
// u_kernel<FIRST>: FIRST -> d uniform (b==0); else d = softmax(b[cap,:]).
// Each thread produces an h-PAIR and stores packed uint2 to g_usp.
// grid (KPH/256=4, 64), block 256.
// ============================================================================
template <bool FIRST>
__global__ void __launch_bounds__(256) u_kernel(const float* __restrict__ x) {
    const int cap = blockIdx.y;
    const int tid = threadIdx.x;
    const int hp = blockIdx.x * 256 + tid;                // h-pair index
    __shared__ float d[S_LEN];

    if (!FIRST) {
        if (tid < S_LEN) d[tid] = g_b[cap * S_LEN + tid];
        __syncthreads();
        if (tid < 32) {
            float x0 = d[tid], x1 = d[tid + 32], x2 = d[tid + 64], x3 = d[tid + 96];
            float mx = fmaxf(fmaxf(x0, x1), fmaxf(x2, x3));
            #pragma unroll
            for (int o = 16; o > 0; o >>= 1) mx = fmaxf(mx, __shfl_xor_sync(0xffffffffu, mx, o));
            float e0 = __expf(x0 - mx), e1 = __expf(x1 - mx);
            float e2 = __expf(x2 - mx), e3 = __expf(x3 - mx);
            float s = (e0 + e1) + (e2 + e3);
            #pragma unroll
            for (int o = 16; o > 0; o >>= 1) s += __shfl_xor_sync(0xffffffffu, s, o);
            float inv = 1.0f / s;
            d[tid] = e0 * inv; d[tid + 32] = e1 * inv;
            d[tid + 64] = e2 * inv; d[tid + 96] = e3 * inv;
        }
        __syncthreads();
    }

    const float2* xp = (const float2*)(x + (size_t)cap * S_LEN * H_DIM) + hp;
    float2 a0 = {0.f, 0.f}, a1 = {0.f, 0.f}, a2 = {0.f, 0.f}, a3 = {0.f, 0.f};
    #pragma unroll 8
    for (int s = 0; s < S_LEN; s += 4) {
        float2 v0 = xp[(size_t)(s + 0) * KPH];
        float2 v1 = xp[(size_t)(s + 1) * KPH];
        float2 v2 = xp[(size_t)(s + 2) * KPH];
        float2 v3 = xp[(size_t)(s + 3) * KPH];
        if (FIRST) {
            a0.x += v0.x; a0.y += v0.y;
            a1.x += v1.x; a1.y += v1.y;
            a2.x += v2.x; a2.y += v2.y;
            a3.x += v3.x; a3.y += v3.y;
        } else {
            a0.x = fmaf(d[s + 0], v0.x, a0.x); a0.y = fmaf(d[s + 0], v0.y, a0.y);
            a1.x = fmaf(d[s + 1], v1.x, a1.x); a1.y = fmaf(d[s + 1], v1.y, a1.y);
            a2.x = fmaf(d[s + 2], v2.x, a2.x); a2.y = fmaf(d[s + 2], v2.y, a2.y);
            a3.x = fmaf(d[s + 3], v3.x, a3.x); a3.y = fmaf(d[s + 3], v3.y, a3.y);
        }
    }
    float se = (a0.x + a1.x) + (a2.x + a3.x);
    float so = (a0.y + a1.y) + (a2.y + a3.y);
    if (FIRST) { se *= (1.0f / S_LEN); so *= (1.0f / S_LEN); }
    uint32_t hi, lo;
    pack_split(se, so, hi, lo);
    g_usp[cap * KPH + hp] = make_uint2(hi, lo);
}

// ============================================================================
// gemm_mma<BK_CONTIG>: g_part[kz][m][j] = sum_{k in chunk kz} A[m][k]*Bval(k,j)
//   BK_CONTIG=true  (TN): B = g_Wtn (j-major rows)        (v = c @ W^T)
//   BK_CONTIG=false (NT): B = g_Wnt (k-pair-major rows)   (c = u @ W)
//   A = packed uint2 operand (g_usp or g_csp), row stride KPH.
//   grid (32, 16) = 512 CTAs, block 128. CTA tile M=64 x N=64, K=128 in 4
//   chunks of 32, double-buffered. Staging pure LDG.128->STS.128, zero cvt.
//   Smem: A [64][20] uint2 M-major; B TN [64][20] j-major / NT [16][68] k-major.
// ============================================================================
template <bool BK_CONTIG>
__global__ void __launch_bounds__(128) gemm_mma_kernel(const uint2* __restrict__ Asp) {
    __shared__ uint2 Aa[2][1280];
    __shared__ uint2 Bs[2][1280];

    const int tid = threadIdx.x;
    const int lane = tid & 31;
    const int w = tid >> 5;
    const int j0 = blockIdx.x * 64;
    const int kz = blockIdx.y;
    const int k0p = kz * (KLEN / 2);              // 64 k-pairs per kz

    // ---- A staging: 4 uint4 slots/thread (64 rows x 8 uint4-groups) ----
    int am[4], aq[4];
    const uint2* ap[4];
    #pragma unroll
    for (int i = 0; i < 4; i++) {
        const int s = tid + 128 * i;
        am[i] = s >> 3; aq[i] = (s & 7) * 2;
        ap[i] = Asp + (size_t)am[i] * KPH + k0p + aq[i];
    }
    // ---- B staging: 4 uint4 slots/thread ----
    const uint2* bp[4];
    int bsm[4];
    #pragma unroll
    for (int i = 0; i < 4; i++) {
        const int s = tid + 128 * i;
        if (BK_CONTIG) {
            const int bm = s >> 3, bq = (s & 7) * 2;
            bp[i] = g_Wtn + (size_t)(j0 + bm) * KPH + k0p + bq;
            bsm[i] = bm * 20 + bq;
        } else {
            const int kp = s >> 5, jq = s & 31;
            bp[i] = g_Wnt + (size_t)(k0p + kp) * H_DIM + j0 + 2 * jq;
            bsm[i] = kp * 68 + 2 * jq;
        }
    }

    // prologue: chunk 0 loads
    uint4 av[4], bv[4];
    #pragma unroll
    for (int i = 0; i < 4; i++) {
        av[i] = *(const uint4*)ap[i];
        bv[i] = *(const uint4*)bp[i];
    }

    const int g = lane >> 2, t = lane & 3;
    const int mrow = w * 16 + g;

    float acc[8][4] = {};

    for (int kc = 0; kc < NCHUNK; kc++) {
        const int cur = kc & 1;
        #pragma unroll
        for (int i = 0; i < 4; i++) {
            *(uint4*)&Aa[cur][am[i] * 20 + aq[i]] = av[i];
            *(uint4*)&Bs[cur][bsm[i]] = bv[i];
        }
        __syncthreads();

        if (kc + 1 < NCHUNK) {
            const int kop = (kc + 1) * KPC;
            #pragma unroll
            for (int i = 0; i < 4; i++) {
                av[i] = *(const uint4*)(ap[i] + kop);
                bv[i] = *(const uint4*)(bp[i] + (BK_CONTIG ? (size_t)kop
                                                           : (size_t)kop * H_DIM));
            }
        }

        #pragma unroll
        for (int half = 0; half < 2; half++) {
            const int o2 = half * 8;
            const uint2 a0 = Aa[cur][mrow * 20 + o2 + t];
            const uint2 a1 = Aa[cur][(mrow + 8) * 20 + o2 + t];
            const uint2 a2 = Aa[cur][mrow * 20 + o2 + t + 4];
            const uint2 a3 = Aa[cur][(mrow + 8) * 20 + o2 + t + 4];
            const uint32_t ah[4] = {a0.x, a1.x, a2.x, a3.x};
            const uint32_t al[4] = {a0.y, a1.y, a2.y, a3.y};
            #pragma unroll
            for (int nt = 0; nt < 8; nt++) {
                const int bn = nt * 8 + g;
                uint2 b0, b1;
                if (BK_CONTIG) {
                    b0 = Bs[cur][bn * 20 + o2 + t];
                    b1 = Bs[cur][bn * 20 + o2 + t + 4];
                } else {
                    b0 = Bs[cur][(o2 + t) * 68 + bn];
                    b1 = Bs[cur][(o2 + t + 4) * 68 + bn];
                }
                mma_bf16(acc[nt], ah, b0.x, b1.x);   // hi*hi
                mma_bf16(acc[nt], ah, b0.y, b1.y);   // hi*lo
                mma_bf16(acc[nt], al, b0.x, b1.x);   // lo*hi
            }
        }
        // single barrier per chunk: stores for chunk kc+2 (same buffer) happen
        // only after barrier kc+1, which all warps reach after reading chunk kc.
    }

    // epilogue: c0=(g,2t) c1=(g,2t+1) c2=(g+8,2t) c3=(g+8,2t+1) per n-tile
    #pragma unroll
    for (int nt = 0; nt < 8; nt++) {
        const int col = j0 + nt * 8 + 2 * t;
        *(float2*)&g_part[kz][mrow    ][col] = make_float2(acc[nt][0], acc[nt][1]);
        *(float2*)&g_part[kz][mrow + 8][col] = make_float2(acc[nt][2], acc[nt][3]);
    }
}

// ============================================================================
// z-split reduce (16 planes): lane = (zq<<3)|jj; each lane sums 4 planes, then
// 2 shfl rounds (fixed order, deterministic).
// ============================================================================
static __device__ __forceinline__ float4 zsplit_sum(int cap, int j, int zq) {
    float4 a = make_float4(0.f, 0.f, 0.f, 0.f);
    #pragma unroll
    for (int i = 0; i < 4; i++) {
        float4 p = *(const float4*)&g_part[zq * 4 + i][cap][j];
        a.x += p.x; a.y += p.y; a.z += p.z; a.w += p.w;
    }
    #pragma unroll
    for (int o = 8; o <= 16; o <<= 1) {
        a.x += __shfl_xor_sync(0xffffffffu, a.x, o);
        a.y += __shfl_xor_sync(0xffffffffu, a.y, o);
        a.z += __shfl_xor_sync(0xffffffffu, a.z, o);
        a.w += __shfl_xor_sync(0xffffffffu, a.w, o);
    }
    return a;
}

// ============================================================================
// reduce_c_norm: out[cap][:] = sum_z g_part[z][cap][:] (RAW c, f32) AND packed
// bf16 split to g_csp (TN gemm A operand); g_nrm2 norm partials.
//   grid (16, 64) = 1024 CTAs, block 128.
// ============================================================================
__global__ void __launch_bounds__(128) reduce_c_norm_kernel(float* __restrict__ out) {
    const int cap = blockIdx.y;
    const int jb = blockIdx.x;
    const int tid = threadIdx.x;
    const int w = tid >> 5, lane = tid & 31;
    const int jj = lane & 7, zq = lane >> 3;
    const int j = (jb * 32 + w * 8 + jj) * 4;

    float4 a = zsplit_sum(cap, j, zq);
    if (zq == 0) {
        *(float4*)(out + cap * H_DIM + j) = a;
        uint32_t h0, l0, h1, l1;
        pack_split(a.x, a.y, h0, l0);
        pack_split(a.z, a.w, h1, l1);
        *(uint4*)&g_csp[cap * KPH + j / 2] = make_uint4(h0, l0, h1, l1);
    }

    float sq = a.x * a.x + a.y * a.y + a.z * a.z + a.w * a.w;
    #pragma unroll
    for (int o = 1; o <= 4; o <<= 1) sq += __shfl_xor_sync(0xffffffffu, sq, o);
    __shared__ float ws[4];
    if (lane == 0) ws[w] = sq;
    __syncthreads();
    if (tid == 0) g_nrm2[cap][jb] = (ws[0] + ws[1]) + (ws[2] + ws[3]);
}

// ============================================================================
// squash_scale (final iteration only): coeff from 16 norm partials; scale out.
// ============================================================================
__global__ void __launch_bounds__(256) squash_scale_kernel(float* __restrict__ out) {
    const int cap = blockIdx.x;
    const int tid = threadIdx.x;
    __shared__ float coeff_s;
    if (tid == 0) {
        float s = 0.f;
        #pragma unroll
        for (int k = 0; k < 16; k++) s += g_nrm2[cap][k];
        coeff_s = s / (1.0f + s) / sqrtf(s + 1e-9f);
    }
    __syncthreads();
    const float co = coeff_s;
    float* row = out + cap * H_DIM;
    #pragma unroll
    for (int r = 0; r < 2; r++) {
        int j = (tid + 256 * r) * 4;
        float4 v = *(float4*)(row + j);
        *(float4*)(row + j) = make_float4(v.x * co, v.y * co, v.z * co, v.w * co);
    }
}

// ============================================================================
// b_update<FIRST> (fused): coeff from g_nrm2; v = co * sum_z part[z][cap][:]
// -> smem; b[cap,s] (=|+=) x[cap,s,:] . v.  grid (4, 64), block 1024; warp/s.
// ============================================================================
template <bool FIRST>
__global__ void __launch_bounds__(1024) b_update_kernel(const float* __restrict__ x) {
    const int cap = blockIdx.y;
    const int sb = blockIdx.x;
    const int tid = threadIdx.x;
    __shared__ float vs[H_DIM];
    __shared__ float coeff_s;

    if (tid == 0) {
        float s = 0.f;
        #pragma unroll
        for (int k = 0; k < 16; k++) s += g_nrm2[cap][k];
        coeff_s = s / (1.0f + s) / sqrtf(s + 1e-9f);
    }
    __syncthreads();
    const float co = coeff_s;

    if (tid < 512) {
        const int j = tid * 4;
        float4 a = make_float4(0.f, 0.f, 0.f, 0.f);
        #pragma unroll
        for (int z = 0; z < KSPLIT; z++) {
            float4 p = *(const float4*)&g_part[z][cap][j];
            a.x += p.x; a.y += p.y; a.z += p.z; a.w += p.w;
        }
        *(float4*)(vs + j) = make_float4(a.x * co, a.y * co, a.z * co, a.w * co);
    }
    __syncthreads();

    const int warp = tid >> 5, lane = tid & 31;
    const int s = sb * 32 + warp;
    const float4* xp = (const float4*)(x + ((size_t)cap * S_LEN + s) * H_DIM);
    const float4* vp = (const float4*)vs;
    float acc = 0.f;
    #pragma unroll 4
    for (int j = lane; j < H_DIM / 4; j += 32) {
        float4 ev = xp[j], cv = vp[j];
        acc = fmaf(ev.x, cv.x, acc);
        acc = fmaf(ev.y, cv.y, acc);
        acc = fmaf(ev.z, cv.z, acc);
        acc = fmaf(ev.w, cv.w, acc);
    }
    #pragma unroll
    for (int o = 16; o > 0; o >>= 1) acc += __shfl_xor_sync(0xffffffffu, acc, o);
    if (lane == 0) {
        if (FIRST) g_b[cap * S_LEN + s] = acc;
        else       g_b[cap * S_LEN + s] += acc;
    }
}

// ============================================================================
// kernel_launch
// ============================================================================
extern "C" void kernel_launch(void* const* d_in, const int* in_sizes, int n_in,
                              void* d_out, int out_size) {
    const float* x = (const float*)d_in[0];   // [64,128,2048] fp32
    const float* W = (const float*)d_in[1];   // [2048,2048] fp32
    float* out = (float*)d_out;               // [64,2048] fp32 — holds c

    uint2 *usp_ptr, *csp_ptr;
    cudaGetSymbolAddress((void**)&usp_ptr, g_usp);
    cudaGetSymbolAddress((void**)&csp_ptr, g_csp);

    const dim3 gemm_grid(H_DIM / 64, KSPLIT);
    const dim3 ugrid(KPH / 256, C_CAPS);
    const dim3 rgrid(16, C_CAPS);
    const dim3 bgrid(4, C_CAPS);

    // W pre-pack (once per call; loop-invariant across the 3 iterations)
    pre_tn_kernel<<<H_DIM * (H_DIM / 4) / 256, 256>>>(W);
    pre_nt_kernel<<<KPH * (H_DIM / 4) / 256, 256>>>(W);

    // iteration 0 (b == 0: uniform softmax; b stored, not accumulated)
    u_kernel<true><<<ugrid, 256>>>(x);
    gemm_mma_kernel<false><<<gemm_grid, 128>>>(usp_ptr);
    reduce_c_norm_kernel<<<rgrid, 128>>>(out);
    gemm_mma_kernel<true><<<gemm_grid, 128>>>(csp_ptr);
    b_update_kernel<true><<<bgrid, 1024>>>(x);

    // iteration 1
    u_kernel<false><<<ugrid, 256>>>(x);
    gemm_mma_kernel<false><<<gemm_grid, 128>>>(usp_ptr);
    reduce_c_norm_kernel<<<rgrid, 128>>>(out);
    gemm_mma_kernel<true><<<gemm_grid, 128>>>(csp_ptr);
    b_update_kernel<false><<<bgrid, 1024>>>(x);

    // iteration 2 (final: squash the output)
    u_kernel<false><<<ugrid, 256>>>(x);
    gemm_mma_kernel<false><<<gemm_grid, 128>>>(usp_ptr);
    reduce_c_norm_kernel<<<rgrid, 128>>>(out);
    squash_scale_kernel<<<C_CAPS, 256>>>(out);
}